// round 15
// baseline (speedup 1.0000x reference)
#include <cuda_runtime.h>
#include <cstdint>
#include <cstddef>

// CTC loss (faithful to reference incl. input_len = C bug).
// B=512, T=512 (row stride), C=128, Tu=128, L=64, S=129, blank=127.
// FORWARD/BACKWARD SPLIT (R13) + deep staging (R14) + TWO-STEP COMPOSED body:
// a3-updates are lane-local, so each pair of timesteps computes step1 fully,
// then step2's a3 locally, then issues BOTH shuffles back-to-back (overlapped
// latency), then finishes step2. Halves the serialized cross-lane exposure.

#define B_    512
#define T_    512
#define C_    128
#define L_    64
#define BLANK 127
#define LN2F  0.69314718055994530942f

#define CHUNK  8
#define NBUF   6

__device__ __forceinline__ void cpasync16(uint32_t saddr, const void* g) {
    asm volatile("cp.async.cg.shared.global [%0], [%1], 16;" :: "r"(saddr), "l"(g));
}
__device__ __forceinline__ void cp_commit() { asm volatile("cp.async.commit_group;"); }
template <int N>
__device__ __forceinline__ void cp_wait() {
    asm volatile("cp.async.wait_group %0;" :: "n"(N));
}
__device__ __forceinline__ float lds(uint32_t addr) {
    float v; asm volatile("ld.shared.f32 %0, [%1];" : "=f"(v) : "r"(addr));
    return v;
}

#define STG_F (2 * NBUF * CHUNK * C_)         // 12288 floats = 48 KB
#define SMEM_BYTES (STG_F * 4 + 132 * 4 + 16)

__global__ __launch_bounds__(64)
void ctc_kernel(const int* __restrict__ y_true,
                const float* __restrict__ y_pred,
                float* __restrict__ out)
{
    extern __shared__ float smem_dyn[];
    float* stg  = smem_dyn;                   // [2][NBUF][CHUNK][C_]
    float* xch  = smem_dyn + STG_F;           // [132] C_64 by state s
    int*   etBp = (int*)(xch + 132);

    const unsigned FULL = 0xffffffffu;
    const int lane = threadIdx.x & 31;
    const int role = threadIdx.x >> 5;        // 0 = forward, 1 = backward
    const int b    = blockIdx.x;

    const uint32_t smb = (uint32_t)__cvta_generic_to_shared(
        stg + (size_t)role * NBUF * CHUNK * C_);
    const float* __restrict__ row = y_pred + (size_t)b * T_ * C_;
    const int2* labp = (const int2*)(y_true + b * L_);

    // ---- per-lane classes / skip flags (R13-validated mapping) ---------------
    int cls0, cls1;
    bool sk1, sk3;
    if (role == 0) {
        const int2 lp = labp[lane];                        // lab[2l], lab[2l+1]
        cls0 = lp.x; cls1 = lp.y;
        const int prev = __shfl_up_sync(FULL, lp.y, 1);    // lab[2l-1]
        sk1 = (lane > 0) && (cls0 != prev);
        sk3 = (cls1 != cls0);
    } else {
        const int2 lp = labp[31 - lane];                   // lab[62-2l], lab[63-2l]
        cls0 = lp.y;
        cls1 = lp.x;
        const int nb = __shfl_up_sync(FULL, lp.x, 1);      // lab[64-2l]
        sk1 = (lane > 0) && (nb != cls0);
        sk3 = (cls0 != cls1);
    }
    const uint32_t ad0 = smb + (uint32_t)cls0 * 4u;
    const uint32_t ad1 = smb + (uint32_t)cls1 * 4u;
    const uint32_t adB = smb + (uint32_t)BLANK * 4u;

    const float* gsrc = row + lane * 4;

    // ---- alpha / C state (identical shape both roles) ------------------------
    float a0 = (lane == 0) ? 1.f : 0.f;
    float a1 = 0.f, a2 = 0.f, a3 = 0.f, a4 = 0.f;
    float n3 = 0.f;
    int etot = 0;

    // ---- staging helper: chunk cc -> buffer bb -------------------------------
    auto stage = [&](int cc, int bb) {
        const int t0 = (role == 0) ? (cc * CHUNK) : (120 - cc * CHUNK);
        #pragma unroll
        for (int j = 0; j < CHUNK; ++j)
            cpasync16(smb + (uint32_t)((bb * CHUNK + j) * C_ + lane * 4) * 4u,
                      gsrc + (size_t)(t0 + j) * C_);
        cp_commit();
    };

    // ---- compute helper: 4 composed PAIRS from buffer bb + rescale -----------
    auto compute = [&](int bb) {
        const uint32_t boff = (uint32_t)(bb * CHUNK * C_) * 4u;
        #pragma unroll
        for (int p = 0; p < CHUNK / 2; ++p) {
            // forward: rows (2p, 2p+1); backward: rows (7-2p, 6-2p)
            const int s1 = (role == 0) ? (2 * p)     : (7 - 2 * p);
            const int s2 = (role == 0) ? (2 * p + 1) : (6 - 2 * p);
            const uint32_t so1 = boff + (uint32_t)(s1 * C_) * 4u;
            const uint32_t so2 = boff + (uint32_t)(s2 * C_) * 4u;
            const float q0 = lds(ad0 + so1);
            const float q1 = lds(ad1 + so1);
            const float qB = lds(adB + so1);
            const float r0 = lds(ad0 + so2);
            const float r1 = lds(ad1 + so2);
            const float rB = lds(adB + so2);

            // ---- step 1 (uses n3) ----
            const float n3s = sk1 ? n3 : 0.f;
            const float a1s = sk3 ? a1 : 0.f;
            const float na3 = (a3 + a2 + a1s) * q1;        // lane-local
            const float na0 = (a0 + n3) * qB;
            const float na1 = (a1 + a0 + n3s) * q0;
            const float na2 = (a2 + a1) * qB;
            const float na4 = (a4 + a3) * qB;

            // ---- step 2's a3 (still lane-local) ----
            const float na1s = sk3 ? na1 : 0.f;
            const float nna3 = (na3 + na2 + na1s) * r1;

            // ---- both shuffles back-to-back (latencies overlap) ----
            const float t1 = __shfl_up_sync(FULL, na3, 1);
            const float t2 = __shfl_up_sync(FULL, nna3, 1);
            const float m3 = (lane == 0) ? 0.f : t1;

            // ---- finish step 2 ----
            const float m3s  = sk1 ? m3 : 0.f;
            const float nna0 = (na0 + m3) * rB;
            const float nna1 = (na1 + na0 + m3s) * r0;
            const float nna2 = (na2 + na1) * rB;
            const float nna4 = (na4 + na3) * rB;

            a0 = nna0; a1 = nna1; a2 = nna2; a3 = nna3; a4 = nna4;
            n3 = (lane == 0) ? 0.f : t2;
        }
        // power-of-two rescale (alpha >= 0 -> float bits monotonic as s32)
        float mv = fmaxf(fmaxf(a0, a1), fmaxf(fmaxf(a2, a3), a4));
        int rb;
        asm volatile("redux.sync.max.s32 %0, %1, 0xffffffff;"
                     : "=r"(rb) : "r"(__float_as_int(mv)));
        const int e = (rb >> 23) - 127;
        const float sc = __int_as_float((127 - e) << 23);  // 2^-e
        a0 *= sc; a1 *= sc; a2 *= sc; a3 *= sc; a4 *= sc; n3 *= sc;
        etot += e;
    };

    // ---- prologue: issue ALL 6 buffered chunks --------------------------------
    #pragma unroll
    for (int k = 0; k < NBUF; ++k) stage(k, k);

    // ---- steady sequence, compile-time wait immediates ------------------------
    cp_wait<5>(); __syncwarp(); compute(0); stage(6, 0);   // chunk 0; refill buf0
    cp_wait<5>(); __syncwarp(); compute(1); stage(7, 1);   // chunk 1; refill buf1
    cp_wait<5>(); __syncwarp(); compute(2);
    cp_wait<4>(); __syncwarp(); compute(3);
    cp_wait<3>(); __syncwarp(); compute(4);
    cp_wait<2>(); __syncwarp(); compute(5);
    cp_wait<1>(); __syncwarp(); compute(0);                // chunk 6 (buf0)
    cp_wait<0>(); __syncwarp(); compute(1);                // chunk 7 (buf1)

    // ---- combine ---------------------------------------------------------------
    if (role == 1) {
        xch[128 - (4 * lane + 0)] = a0;
        xch[128 - (4 * lane + 1)] = a1;
        xch[128 - (4 * lane + 2)] = a2;
        xch[128 - (4 * lane + 3)] = a3;
        if (lane == 31) { xch[0] = a4; *etBp = etot; }     // tau=128 -> s=0
    }
    __syncthreads();

    if (role == 0) {
        const float n3s = sk1 ? n3 : 0.f;
        const float a1s = sk3 ? a1 : 0.f;
        const float p0 = a0 + n3;
        const float p1 = a1 + a0 + n3s;
        const float p2 = a2 + a1;
        const float p3 = a3 + a2 + a1s;
        const float p4 = a4 + a3;

        float dot = p0 * xch[4 * lane + 0]
                  + p1 * xch[4 * lane + 1]
                  + p2 * xch[4 * lane + 2]
                  + p3 * xch[4 * lane + 3];
        if (lane == 31) dot += p4 * xch[128];

        #pragma unroll
        for (int k = 16; k >= 1; k >>= 1)
            dot += __shfl_xor_sync(FULL, dot, k);

        if (lane == 0)
            out[b] = -(__logf(dot) + (float)(etot + *etBp) * LN2F);
    }
}

extern "C" void kernel_launch(void* const* d_in, const int* in_sizes, int n_in,
                              void* d_out, int out_size)
{
    const int* y_true;
    const float* y_pred;
    if (n_in >= 2 && in_sizes[0] == B_ * L_) {
        y_true = (const int*)d_in[0];
        y_pred = (const float*)d_in[1];
    } else {
        y_true = (const int*)d_in[1];
        y_pred = (const float*)d_in[0];
    }
    float* out = (float*)d_out;

    cudaFuncSetAttribute(ctc_kernel,
                         cudaFuncAttributeMaxDynamicSharedMemorySize, SMEM_BYTES);

    ctc_kernel<<<B_, 64, SMEM_BYTES>>>(y_true, y_pred, out);
}